// round 1
// baseline (speedup 1.0000x reference)
#include <cuda_runtime.h>
#include <math.h>

#define NTAPS 201
#define HALF  100
#define TILE  256
#define WIN   (TILE + 208)   // need TILE+205 window entries

// Shared window of scaled complex x (both channels packed per position):
//   sx[idx] = { re0, im0, re1, im1 } at global position g = l0 - 2 + idx (mod M)
// Weights packed per tap j (3 float4, broadcast reads):
//   swt[3j+0] = { ixpm_w[j], icixpm_w[j], wr[0][j], wi[0][j] }
//   swt[3j+1] = { wr[1][j],  wi[1][j],    wr[2][j], wi[2][j] }
//   swt[3j+2] = { wr[3][j],  wi[3][j],    0, 0 }
// Filter index k maps to shift s_k in {-2,-1,1,2}.

__global__ __launch_bounds__(TILE)
void snse_kernel(const float* __restrict__ x_real,
                 const float* __restrict__ x_imag,
                 const float* __restrict__ task_info,
                 const float* __restrict__ C00p,
                 const float* __restrict__ ixpm_w,
                 const float* __restrict__ icixpm_w,
                 const float* __restrict__ fwm_wr,
                 const float* __restrict__ fwm_wi,
                 float* __restrict__ out,
                 int M, int Lout)
{
    __shared__ float4 sx[WIN];
    __shared__ float4 swt[NTAPS * 3];

    const int b  = blockIdx.y;
    const int l0 = blockIdx.x * TILE;
    const int t  = threadIdx.x;

    const float dbm = task_info[b * 4];
    const float P   = exp10f(dbm * 0.1f) * 0.5f;   // /Nm, Nm=2
    const float sP  = sqrtf(P);
    const float rsP = 1.0f / sP;
    const float C00 = C00p[0];

    // ---- load weights into shared ----
    for (int j = t; j < NTAPS; j += TILE) {
        float w0  = ixpm_w[j];
        float w1  = icixpm_w[j];
        float wr0 = fwm_wr[0 * NTAPS + j], wr1 = fwm_wr[1 * NTAPS + j];
        float wr2 = fwm_wr[2 * NTAPS + j], wr3 = fwm_wr[3 * NTAPS + j];
        float wi0 = fwm_wi[0 * NTAPS + j], wi1 = fwm_wi[1 * NTAPS + j];
        float wi2 = fwm_wi[2 * NTAPS + j], wi3 = fwm_wi[3 * NTAPS + j];
        swt[3 * j + 0] = make_float4(w0,  w1,  wr0, wi0);
        swt[3 * j + 1] = make_float4(wr1, wi1, wr2, wi2);
        swt[3 * j + 2] = make_float4(wr3, wi3, 0.f, 0.f);
    }

    // ---- load scaled x window with mod-M wrap (reproduces jnp.roll edges) ----
    const float* xr = x_real + (size_t)b * M * 2;
    const float* xi = x_imag + (size_t)b * M * 2;
    for (int idx = t; idx < WIN; idx += TILE) {
        int g  = l0 - 2 + idx;
        int gm = (g < 0) ? g + M : ((g >= M) ? g - M : g);
        float r0 = xr[gm * 2 + 0], r1 = xr[gm * 2 + 1];
        float i0 = xi[gm * 2 + 0], i1 = xi[gm * 2 + 1];
        sx[idx] = make_float4(r0 * sP, i0 * sP, r1 * sP, i1 * sP);
    }
    __syncthreads();

    const int l = l0 + t;

    // ---- accumulators ----
    float axp0 = 0.f, axp1 = 0.f;       // ixpm conv (per channel)
    float qcr = 0.f, qci = 0.f;         // icixpm conv of q0 (q1 = conj(q0))
    float G00r[4], G00i[4], G11r[4], G11i[4];
    float G01r[4], G01i[4], G10r[4], G10i[4];
#pragma unroll
    for (int k = 0; k < 4; ++k) {
        G00r[k] = G00i[k] = G11r[k] = G11i[k] = 0.f;
        G01r[k] = G01i[k] = G10r[k] = G10i[k] = 0.f;
    }

    // ring holds X at positions p-2..p+1; load p+2 each tap (p = l + j)
    float4 ra = sx[t + 0];
    float4 rb = sx[t + 1];
    float4 rc = sx[t + 2];
    float4 rd = sx[t + 3];

    for (int j = 0; j < NTAPS; ++j) {
        float4 re_ = sx[t + j + 4];          // position p+2
        float4 w0 = swt[3 * j + 0];
        float4 w1 = swt[3 * j + 1];
        float4 w2 = swt[3 * j + 2];

        // center = rc (position p = l + j)
        float p0 = rc.x * rc.x + rc.y * rc.y;
        float p1 = rc.z * rc.z + rc.w * rc.w;
        float ps0 = 2.f * p0 + p1;
        float ps1 = 2.f * p1 + p0;
        axp0 += w0.x * ps0;
        axp1 += w0.x * ps1;

        float q0r = rc.x * rc.z + rc.y * rc.w;
        float q0i = rc.y * rc.z - rc.x * rc.w;
        qcr += w0.y * q0r;
        qci += w0.y * q0i;

        // shift order k=0..3 <-> s = -2,-1,1,2 -> X[p-s] = re_, rd, rb, ra
        float4 cp[4];
        cp[0] = re_; cp[1] = rd; cp[2] = rb; cp[3] = ra;
        float wr[4], wi[4];
        wr[0] = w0.z; wi[0] = w0.w;
        wr[1] = w1.x; wi[1] = w1.y;
        wr[2] = w1.z; wi[2] = w1.w;
        wr[3] = w2.x; wi[3] = w2.y;

#pragma unroll
        for (int k = 0; k < 4; ++k) {
            float4 cc = cp[k];
            // P_mm' = X[p][m] * conj(X[p-s][m'])
            float P00r = rc.x * cc.x + rc.y * cc.y, P00i = rc.y * cc.x - rc.x * cc.y;
            float P11r = rc.z * cc.z + rc.w * cc.w, P11i = rc.w * cc.z - rc.z * cc.w;
            float P01r = rc.x * cc.z + rc.y * cc.w, P01i = rc.y * cc.z - rc.x * cc.w;
            float P10r = rc.z * cc.x + rc.w * cc.y, P10i = rc.w * cc.x - rc.z * cc.y;
            float wkr = wr[k], wki = wi[k];
            G00r[k] += wkr * P00r - wki * P00i;  G00i[k] += wkr * P00i + wki * P00r;
            G11r[k] += wkr * P11r - wki * P11i;  G11i[k] += wkr * P11i + wki * P11r;
            G01r[k] += wkr * P01r - wki * P01i;  G01i[k] += wkr * P01i + wki * P01r;
            G10r[k] += wkr * P10r - wki * P10i;  G10i[k] += wkr * P10i + wki * P10r;
        }

        // rotate ring
        ra = rb; rb = rc; rc = rd; rd = re_;
    }

    if (l < Lout) {
        // ---- center-tap corrections (zcv) ----
        float4 xc = sx[t + 102];                // position l + 100
        float pc0 = xc.x * xc.x + xc.y * xc.y;
        float pc1 = xc.z * xc.z + xc.w * xc.w;
        float psc0 = 2.f * pc0 + pc1;
        float psc1 = 2.f * pc1 + pc0;
        float4 wc = swt[3 * HALF];
        axp0 -= wc.x * psc0;
        axp1 -= wc.x * psc1;
        float qc0r_c = xc.x * xc.z + xc.y * xc.w;
        float qc0i_c = xc.y * xc.z - xc.x * xc.w;
        qcr -= wc.y * qc0r_c;
        qci -= wc.y * qc0i_c;

        float spm  = C00 * (pc0 + pc1);
        float phi0 = spm + 2.f * axp0;
        float phi1 = spm + 2.f * axp1;

        // ---- ici ----  ici[m] = i * X_c[1-m] * qc[m],  qc[1]=conj(qc[0])
        float ici0r = -(xc.z * qci + xc.w * qcr);
        float ici0i =   xc.z * qcr - xc.w * qci;
        float ici1r =   xc.x * qci - xc.y * qcr;
        float ici1i =   xc.x * qcr + xc.y * qci;

        // ---- FWM combine ----
        // fA[k][0]=2G00+G11, fA[k][1]=2G11+G00, fB[k][0]=G01, fB[k][1]=G10
        // Xs[k] = X[l+100-s_k]: shared offsets t+102-s_k for s={-2,-1,1,2}
        float fwm0r = 0.f, fwm0i = 0.f, fwm1r = 0.f, fwm1i = 0.f;
        const int soff[4] = {104, 103, 101, 100};
#pragma unroll
        for (int k = 0; k < 4; ++k) {
            float4 xs = sx[t + soff[k]];
            float fA0r = 2.f * G00r[k] + G11r[k], fA0i = 2.f * G00i[k] + G11i[k];
            float fA1r = 2.f * G11r[k] + G00r[k], fA1i = 2.f * G11i[k] + G00i[k];
            float fB0r = G01r[k], fB0i = G01i[k];
            float fB1r = G10r[k], fB1i = G10i[k];
            // fwm0 += Xs[ch0]*fA0 + Xs[ch1]*fB0   (plain complex multiply)
            fwm0r += xs.x * fA0r - xs.y * fA0i;
            fwm0i += xs.x * fA0i + xs.y * fA0r;
            fwm0r += xs.z * fB0r - xs.w * fB0i;
            fwm0i += xs.z * fB0i + xs.w * fB0r;
            // fwm1 += Xs[ch1]*fA1 + Xs[ch0]*fB1
            fwm1r += xs.z * fA1r - xs.w * fA1i;
            fwm1i += xs.z * fA1i + xs.w * fA1r;
            fwm1r += xs.x * fB1r - xs.y * fB1i;
            fwm1i += xs.x * fB1i + xs.y * fB1r;
        }

        // ---- assemble: trunc(x)*exp(i phi) + ici + fwm, then /sP ----
        float s0, c0, s1, c1;
        sincosf(phi0, &s0, &c0);
        sincosf(phi1, &s1, &c1);
        float o0r = xc.x * c0 - xc.y * s0 + ici0r + fwm0r;
        float o0i = xc.x * s0 + xc.y * c0 + ici0i + fwm0i;
        float o1r = xc.z * c1 - xc.w * s1 + ici1r + fwm1r;
        float o1i = xc.z * s1 + xc.w * c1 + ici1i + fwm1i;

        float4* outv = (float4*)(out + ((size_t)(b * (size_t)Lout + l)) * 4);
        *outv = make_float4(o0r * rsP, o0i * rsP, o1r * rsP, o1i * rsP);
    }
}

extern "C" void kernel_launch(void* const* d_in, const int* in_sizes, int n_in,
                              void* d_out, int out_size)
{
    const float* x_real    = (const float*)d_in[0];
    const float* x_imag    = (const float*)d_in[1];
    const float* task_info = (const float*)d_in[2];
    const float* C00       = (const float*)d_in[3];
    const float* ixpm_w    = (const float*)d_in[4];
    const float* icixpm_w  = (const float*)d_in[5];
    const float* fwm_wr    = (const float*)d_in[6];
    const float* fwm_wi    = (const float*)d_in[7];
    // d_in[8] = i (unused: share=True -> module 0)

    int B = in_sizes[2] / 4;
    int M = in_sizes[0] / (B * 2);
    int Lout = M - NTAPS + 1;

    dim3 grid((Lout + TILE - 1) / TILE, B);
    snse_kernel<<<grid, TILE>>>(x_real, x_imag, task_info, C00,
                                ixpm_w, icixpm_w, fwm_wr, fwm_wi,
                                (float*)d_out, M, Lout);
}

// round 2
// speedup vs baseline: 1.4726x; 1.4726x over previous
#include <cuda_runtime.h>
#include <math.h>

#define NTAPS 201
#define HALF  100
#define NT2   203          // extended tap loop (covers shifted-weight tails)
#define TILE  256
#define WIN   (TILE + 208)

typedef unsigned long long ull;

__device__ __forceinline__ ull pk(float lo, float hi) {
    ull r; asm("mov.b64 %0, {%1, %2};" : "=l"(r) : "f"(lo), "f"(hi)); return r;
}
__device__ __forceinline__ void fma2(ull &d, ull a, ull b) {
    asm("fma.rn.f32x2 %0, %1, %2, %0;" : "+l"(d) : "l"(a), "l"(b));
}
__device__ __forceinline__ float2 upk(ull v) {
    float2 r; asm("mov.b64 {%0, %1}, %2;" : "=f"(r.x), "=f"(r.y) : "l"(v)); return r;
}

// Weight table per tap j (5 float4, all pre-splatted pairs):
//  Wt[5j+0] = (wrP1,wrP1, wiP1,wiP1)   filter 2 (s=+1), w[j] (0 for j>200)
//  Wt[5j+1] = (wrP2,wrP2, wiP2,wiP2)   filter 3 (s=+2), w[j]
//  Wt[5j+2] = (wrM1,wrM1, wiM1,wiM1)   filter 1 (s=-1), w[j-1] (0 outside)
//  Wt[5j+3] = (wrM2,wrM2, wiM2,wiM2)   filter 0 (s=-2), w[j-2]
//  Wt[5j+4] = (wx,wx, wq,wq)           ixpm / icixpm, w[j] (0 for j>200)

__global__ __launch_bounds__(TILE)
void snse_kernel(const float* __restrict__ x_real,
                 const float* __restrict__ x_imag,
                 const float* __restrict__ task_info,
                 const float* __restrict__ C00p,
                 const float* __restrict__ ixpm_w,
                 const float* __restrict__ icixpm_w,
                 const float* __restrict__ fwm_wr,
                 const float* __restrict__ fwm_wi,
                 float* __restrict__ out,
                 int M, int Lout)
{
    __shared__ float4 sx[WIN];
    __shared__ float4 Wt[NT2 * 5];

    const int b  = blockIdx.y;
    const int l0 = blockIdx.x * TILE;
    const int t  = threadIdx.x;

    const float dbm = task_info[b * 4];
    const float P   = exp10f(dbm * 0.1f) * 0.5f;   // /Nm, Nm=2
    const float sP  = sqrtf(P);
    const float rsP = 1.0f / sP;
    const float C00 = C00p[0];

    // ---- build weight table ----
    for (int j = t; j < NT2; j += TILE) {
        float wrP1 = (j <= 200) ? fwm_wr[2 * NTAPS + j] : 0.f;
        float wiP1 = (j <= 200) ? fwm_wi[2 * NTAPS + j] : 0.f;
        float wrP2 = (j <= 200) ? fwm_wr[3 * NTAPS + j] : 0.f;
        float wiP2 = (j <= 200) ? fwm_wi[3 * NTAPS + j] : 0.f;
        float wrM1 = (j >= 1 && j <= 201) ? fwm_wr[1 * NTAPS + (j - 1)] : 0.f;
        float wiM1 = (j >= 1 && j <= 201) ? fwm_wi[1 * NTAPS + (j - 1)] : 0.f;
        float wrM2 = (j >= 2) ? fwm_wr[0 * NTAPS + (j - 2)] : 0.f;
        float wiM2 = (j >= 2) ? fwm_wi[0 * NTAPS + (j - 2)] : 0.f;
        float wx   = (j <= 200) ? ixpm_w[j]   : 0.f;
        float wq   = (j <= 200) ? icixpm_w[j] : 0.f;
        Wt[5 * j + 0] = make_float4(wrP1, wrP1, wiP1, wiP1);
        Wt[5 * j + 1] = make_float4(wrP2, wrP2, wiP2, wiP2);
        Wt[5 * j + 2] = make_float4(wrM1, wrM1, wiM1, wiM1);
        Wt[5 * j + 3] = make_float4(wrM2, wrM2, wiM2, wiM2);
        Wt[5 * j + 4] = make_float4(wx,   wx,   wq,   wq);
    }

    // ---- load scaled x window with mod-M wrap ----
    const float* xr = x_real + (size_t)b * M * 2;
    const float* xi = x_imag + (size_t)b * M * 2;
    for (int idx = t; idx < WIN; idx += TILE) {
        int g  = l0 - 2 + idx;
        int gm = (g < 0) ? g + M : ((g >= M) ? g - M : g);
        float r0 = xr[gm * 2 + 0], r1 = xr[gm * 2 + 1];
        float i0 = xi[gm * 2 + 0], i1 = xi[gm * 2 + 1];
        sx[idx] = make_float4(r0 * sP, i0 * sP, r1 * sP, i1 * sP);
    }
    __syncthreads();

    const int l = l0 + t;

    // ---- accumulators (f32x2 pairs) ----
    // [s][mm']: s index 0 -> shift +1 products, 1 -> shift +2; mm' 0=00,1=01,2=10,3=11
    ull Ap[8], Bp[8], Am[8], Bm[8];
#pragma unroll
    for (int k = 0; k < 8; ++k) { Ap[k] = Bp[k] = Am[k] = Bm[k] = 0ULL; }
    ull axp = 0ULL;   // (axp0, axp1)  ixpm
    ull qc  = 0ULL;   // (qcr, qci)    icixpm conv of q0

    // ring: ra = X[p-2], rb = X[p-1], rc = X[p],  p = l + j
    float4 ra = sx[t + 0];
    float4 rb = sx[t + 1];
    float4 rc = sx[t + 2];

#pragma unroll 2
    for (int j = 0; j < NT2; ++j) {
        float4 nx = sx[t + j + 3];
        float4 w0 = Wt[5 * j + 0];
        float4 w1 = Wt[5 * j + 1];
        float4 w2 = Wt[5 * j + 2];
        float4 w3 = Wt[5 * j + 3];
        float4 w4 = Wt[5 * j + 4];

        ull wrP1 = pk(w0.x, w0.y), wiP1 = pk(w0.z, w0.w);
        ull wrP2 = pk(w1.x, w1.y), wiP2 = pk(w1.z, w1.w);
        ull wrM1 = pk(w2.x, w2.y), wiM1 = pk(w2.z, w2.w);
        ull wrM2 = pk(w3.x, w3.y), wiM2 = pk(w3.z, w3.w);

        // ---- ixpm / icixpm (center rc) ----
        float p0 = rc.x * rc.x + rc.y * rc.y;
        float p1 = rc.z * rc.z + rc.w * rc.w;
        float ps0 = 2.f * p0 + p1;
        float ps1 = 2.f * p1 + p0;
        fma2(axp, pk(ps0, ps1), pk(w4.x, w4.y));
        float q0r = rc.x * rc.z + rc.y * rc.w;
        float q0i = rc.y * rc.z - rc.x * rc.w;
        fma2(qc, pk(q0r, q0i), pk(w4.z, w4.w));

        // ---- shift +1 products: D = X[p] * conj(X[p-1]) (c = rb) ----
        {
            float Dr, Di; ull d;
            Dr = rc.x * rb.x + rc.y * rb.y;  Di = rc.y * rb.x - rc.x * rb.y;
            d = pk(Dr, Di);
            fma2(Ap[0], d, wrP1); fma2(Bp[0], d, wiP1);
            fma2(Am[0], d, wrM1); fma2(Bm[0], d, wiM1);
            Dr = rc.x * rb.z + rc.y * rb.w;  Di = rc.y * rb.z - rc.x * rb.w;
            d = pk(Dr, Di);
            fma2(Ap[1], d, wrP1); fma2(Bp[1], d, wiP1);
            fma2(Am[1], d, wrM1); fma2(Bm[1], d, wiM1);
            Dr = rc.z * rb.x + rc.w * rb.y;  Di = rc.w * rb.x - rc.z * rb.y;
            d = pk(Dr, Di);
            fma2(Ap[2], d, wrP1); fma2(Bp[2], d, wiP1);
            fma2(Am[2], d, wrM1); fma2(Bm[2], d, wiM1);
            Dr = rc.z * rb.z + rc.w * rb.w;  Di = rc.w * rb.z - rc.z * rb.w;
            d = pk(Dr, Di);
            fma2(Ap[3], d, wrP1); fma2(Bp[3], d, wiP1);
            fma2(Am[3], d, wrM1); fma2(Bm[3], d, wiM1);
        }
        // ---- shift +2 products: c = ra ----
        {
            float Dr, Di; ull d;
            Dr = rc.x * ra.x + rc.y * ra.y;  Di = rc.y * ra.x - rc.x * ra.y;
            d = pk(Dr, Di);
            fma2(Ap[4], d, wrP2); fma2(Bp[4], d, wiP2);
            fma2(Am[4], d, wrM2); fma2(Bm[4], d, wiM2);
            Dr = rc.x * ra.z + rc.y * ra.w;  Di = rc.y * ra.z - rc.x * ra.w;
            d = pk(Dr, Di);
            fma2(Ap[5], d, wrP2); fma2(Bp[5], d, wiP2);
            fma2(Am[5], d, wrM2); fma2(Bm[5], d, wiM2);
            Dr = rc.z * ra.x + rc.w * ra.y;  Di = rc.w * ra.x - rc.z * ra.y;
            d = pk(Dr, Di);
            fma2(Ap[6], d, wrP2); fma2(Bp[6], d, wiP2);
            fma2(Am[6], d, wrM2); fma2(Bm[6], d, wiM2);
            Dr = rc.z * ra.z + rc.w * ra.w;  Di = rc.w * ra.z - rc.z * ra.w;
            d = pk(Dr, Di);
            fma2(Ap[7], d, wrP2); fma2(Bp[7], d, wiP2);
            fma2(Am[7], d, wrM2); fma2(Bm[7], d, wiM2);
        }

        ra = rb; rb = rc; rc = nx;
    }

    if (l < Lout) {
        float2 axpf = upk(axp);
        float2 qcf  = upk(qc);
        float axp0 = axpf.x, axp1 = axpf.y;
        float qcr = qcf.x, qci = qcf.y;

        // ---- center-tap corrections (zcv) ----
        float4 xc = sx[t + 102];               // position l + 100
        float wxc = ixpm_w[HALF];
        float wqc = icixpm_w[HALF];
        float pc0 = xc.x * xc.x + xc.y * xc.y;
        float pc1 = xc.z * xc.z + xc.w * xc.w;
        axp0 -= wxc * (2.f * pc0 + pc1);
        axp1 -= wxc * (2.f * pc1 + pc0);
        qcr -= wqc * (xc.x * xc.z + xc.y * xc.w);
        qci -= wqc * (xc.y * xc.z - xc.x * xc.w);

        float spm  = C00 * (pc0 + pc1);
        float phi0 = spm + 2.f * axp0;
        float phi1 = spm + 2.f * axp1;

        // ---- ici ----
        float ici0r = -(xc.z * qci + xc.w * qcr);
        float ici0i =   xc.z * qcr - xc.w * qci;
        float ici1r =   xc.x * qci - xc.y * qcr;
        float ici1i =   xc.x * qcr + xc.y * qci;

        // ---- recombine G for the 4 shift-filters k=0..3 (s=-2,-1,1,2) ----
        float Gr[4][4], Gi[4][4];
        const int sw[4] = {0, 2, 1, 3};   // mm' -> m'm
#pragma unroll
        for (int m = 0; m < 4; ++m) {
            float2 a, bb;
            // k=2: s=+1
            a = upk(Ap[m]); bb = upk(Bp[m]);
            Gr[2][m] = a.x - bb.y;  Gi[2][m] = a.y + bb.x;
            // k=3: s=+2
            a = upk(Ap[4 + m]); bb = upk(Bp[4 + m]);
            Gr[3][m] = a.x - bb.y;  Gi[3][m] = a.y + bb.x;
            // k=1: s=-1 : conj-combine with channel swap
            a = upk(Am[sw[m]]); bb = upk(Bm[sw[m]]);
            Gr[1][m] = a.x + bb.y;  Gi[1][m] = bb.x - a.y;
            // k=0: s=-2
            a = upk(Am[4 + sw[m]]); bb = upk(Bm[4 + sw[m]]);
            Gr[0][m] = a.x + bb.y;  Gi[0][m] = bb.x - a.y;
        }

        // ---- FWM combine ----
        float fwm0r = 0.f, fwm0i = 0.f, fwm1r = 0.f, fwm1i = 0.f;
        const int soff[4] = {104, 103, 101, 100};  // s=-2,-1,1,2 -> X[l+100-s]
#pragma unroll
        for (int k = 0; k < 4; ++k) {
            float4 xs = sx[t + soff[k]];
            float G00r = Gr[k][0], G00i = Gi[k][0];
            float G01r = Gr[k][1], G01i = Gi[k][1];
            float G10r = Gr[k][2], G10i = Gi[k][2];
            float G11r = Gr[k][3], G11i = Gi[k][3];
            float fA0r = 2.f * G00r + G11r, fA0i = 2.f * G00i + G11i;
            float fA1r = 2.f * G11r + G00r, fA1i = 2.f * G11i + G00i;
            fwm0r += xs.x * fA0r - xs.y * fA0i;
            fwm0i += xs.x * fA0i + xs.y * fA0r;
            fwm0r += xs.z * G01r - xs.w * G01i;
            fwm0i += xs.z * G01i + xs.w * G01r;
            fwm1r += xs.z * fA1r - xs.w * fA1i;
            fwm1i += xs.z * fA1i + xs.w * fA1r;
            fwm1r += xs.x * G10r - xs.y * G10i;
            fwm1i += xs.x * G10i + xs.y * G10r;
        }

        // ---- assemble ----
        float s0, c0, s1, c1;
        sincosf(phi0, &s0, &c0);
        sincosf(phi1, &s1, &c1);
        float o0r = xc.x * c0 - xc.y * s0 + ici0r + fwm0r;
        float o0i = xc.x * s0 + xc.y * c0 + ici0i + fwm0i;
        float o1r = xc.z * c1 - xc.w * s1 + ici1r + fwm1r;
        float o1i = xc.z * s1 + xc.w * c1 + ici1i + fwm1i;

        float4* outv = (float4*)(out + ((size_t)(b * (size_t)Lout + l)) * 4);
        *outv = make_float4(o0r * rsP, o0i * rsP, o1r * rsP, o1i * rsP);
    }
}

extern "C" void kernel_launch(void* const* d_in, const int* in_sizes, int n_in,
                              void* d_out, int out_size)
{
    const float* x_real    = (const float*)d_in[0];
    const float* x_imag    = (const float*)d_in[1];
    const float* task_info = (const float*)d_in[2];
    const float* C00       = (const float*)d_in[3];
    const float* ixpm_w    = (const float*)d_in[4];
    const float* icixpm_w  = (const float*)d_in[5];
    const float* fwm_wr    = (const float*)d_in[6];
    const float* fwm_wi    = (const float*)d_in[7];

    int B = in_sizes[2] / 4;
    int M = in_sizes[0] / (B * 2);
    int Lout = M - NTAPS + 1;

    dim3 grid((Lout + TILE - 1) / TILE, B);
    snse_kernel<<<grid, TILE>>>(x_real, x_imag, task_info, C00,
                                ixpm_w, icixpm_w, fwm_wr, fwm_wi,
                                (float*)d_out, M, Lout);
}

// round 3
// speedup vs baseline: 1.5003x; 1.0188x over previous
#include <cuda_runtime.h>
#include <math.h>

#define NTAPS 201
#define HALF  100
#define NT2   203          // extended tap loop (covers shifted-weight tails)
#define TILE  128
#define WIN   (TILE + 208)

typedef unsigned long long ull;

__device__ __forceinline__ ull pk(float lo, float hi) {
    ull r; asm("mov.b64 %0, {%1, %2};" : "=l"(r) : "f"(lo), "f"(hi)); return r;
}
__device__ __forceinline__ float2 upk(ull v) {
    float2 r; asm("mov.b64 {%0, %1}, %2;" : "=f"(r.x), "=f"(r.y) : "l"(v)); return r;
}
__device__ __forceinline__ void fma2(ull &d, ull a, ull b) {
    asm("fma.rn.f32x2 %0, %1, %2, %0;" : "+l"(d) : "l"(a), "l"(b));
}
__device__ __forceinline__ ull fma2r(ull a, ull b, ull c) {
    ull r; asm("fma.rn.f32x2 %0, %1, %2, %3;" : "=l"(r) : "l"(a), "l"(b), "l"(c)); return r;
}
__device__ __forceinline__ ull mul2(ull a, ull b) {
    ull r; asm("mul.rn.f32x2 %0, %1, %2;" : "=l"(r) : "l"(a), "l"(b)); return r;
}

// Shared layouts (all 64-bit-operand friendly, no register packs in the hot loop):
//  sU[idx]      = { (r0,i0), (r1,i1) }          natural pairs (u_m)
//  sV[idx]      = { (i0,-r0), (i1,-r1) }        rotated pairs (v_m)
//  sS[2idx+c]   = { (rc,rc), (ic,ic) }          splats per channel c
//  sW[5j+0..4]  = { wrP1s|wiP1s, wrP2s|wiP2s, wrM1s|wiM1s, wrM2s|wiM2s, wxs|wqs }

__global__ __launch_bounds__(TILE, 3)
void snse_kernel(const float* __restrict__ x_real,
                 const float* __restrict__ x_imag,
                 const float* __restrict__ task_info,
                 const float* __restrict__ C00p,
                 const float* __restrict__ ixpm_w,
                 const float* __restrict__ icixpm_w,
                 const float* __restrict__ fwm_wr,
                 const float* __restrict__ fwm_wi,
                 float* __restrict__ out,
                 int M, int Lout)
{
    __shared__ ulonglong2 sU[WIN];
    __shared__ ulonglong2 sV[WIN];
    __shared__ ulonglong2 sS[WIN * 2];
    __shared__ ulonglong2 sW[NT2 * 5];

    const int b  = blockIdx.y;
    const int l0 = blockIdx.x * TILE;
    const int t  = threadIdx.x;

    const float dbm = task_info[b * 4];
    const float P   = exp10f(dbm * 0.1f) * 0.5f;   // /Nm, Nm=2
    const float sP  = sqrtf(P);
    const float rsP = 1.0f / sP;
    const float C00 = C00p[0];

    // ---- build pre-splatted weight table ----
    for (int j = t; j < NT2; j += TILE) {
        float wrP1 = (j <= 200) ? fwm_wr[2 * NTAPS + j] : 0.f;
        float wiP1 = (j <= 200) ? fwm_wi[2 * NTAPS + j] : 0.f;
        float wrP2 = (j <= 200) ? fwm_wr[3 * NTAPS + j] : 0.f;
        float wiP2 = (j <= 200) ? fwm_wi[3 * NTAPS + j] : 0.f;
        float wrM1 = (j >= 1 && j <= 201) ? fwm_wr[1 * NTAPS + (j - 1)] : 0.f;
        float wiM1 = (j >= 1 && j <= 201) ? fwm_wi[1 * NTAPS + (j - 1)] : 0.f;
        float wrM2 = (j >= 2) ? fwm_wr[0 * NTAPS + (j - 2)] : 0.f;
        float wiM2 = (j >= 2) ? fwm_wi[0 * NTAPS + (j - 2)] : 0.f;
        float wx   = (j <= 200) ? ixpm_w[j]   : 0.f;
        float wq   = (j <= 200) ? icixpm_w[j] : 0.f;
        sW[5 * j + 0] = make_ulonglong2(pk(wrP1, wrP1), pk(wiP1, wiP1));
        sW[5 * j + 1] = make_ulonglong2(pk(wrP2, wrP2), pk(wiP2, wiP2));
        sW[5 * j + 2] = make_ulonglong2(pk(wrM1, wrM1), pk(wiM1, wiM1));
        sW[5 * j + 3] = make_ulonglong2(pk(wrM2, wrM2), pk(wiM2, wiM2));
        sW[5 * j + 4] = make_ulonglong2(pk(wx, wx), pk(wq, wq));
    }

    // ---- load scaled x window with mod-M wrap ----
    const float* xr = x_real + (size_t)b * M * 2;
    const float* xi = x_imag + (size_t)b * M * 2;
    for (int idx = t; idx < WIN; idx += TILE) {
        int g  = l0 - 2 + idx;
        int gm = (g < 0) ? g + M : ((g >= M) ? g - M : g);
        float r0 = xr[gm * 2 + 0] * sP, r1 = xr[gm * 2 + 1] * sP;
        float i0 = xi[gm * 2 + 0] * sP, i1 = xi[gm * 2 + 1] * sP;
        sU[idx] = make_ulonglong2(pk(r0, i0), pk(r1, i1));
        sV[idx] = make_ulonglong2(pk(i0, -r0), pk(i1, -r1));
        sS[2 * idx + 0] = make_ulonglong2(pk(r0, r0), pk(i0, i0));
        sS[2 * idx + 1] = make_ulonglong2(pk(r1, r1), pk(i1, i1));
    }
    __syncthreads();

    const int l = l0 + t;

    // ---- accumulators (f32x2 pairs) ----
    ull Ap[8], Bp[8], Am[8], Bm[8];
#pragma unroll
    for (int k = 0; k < 8; ++k) { Ap[k] = Bp[k] = Am[k] = Bm[k] = 0ULL; }
    ull axp = 0ULL;   // (axp0, axp1)
    ull qc  = 0ULL;   // (qcr, qci)

    // splat ring for conjugated positions: cs2 = splats(p-2), cs1 = splats(p-1)
    ulonglong2 cs2a = sS[2 * (t + 0) + 0], cs2b = sS[2 * (t + 0) + 1];
    ulonglong2 cs1a = sS[2 * (t + 1) + 0], cs1b = sS[2 * (t + 1) + 1];

#pragma unroll 2
    for (int j = 0; j < NT2; ++j) {
        const int iw = t + 2 + j;
        ulonglong2 nsa = sS[2 * iw + 0];   // splats of p, ch0: (r0,r0),(i0,i0)
        ulonglong2 nsb = sS[2 * iw + 1];   // ch1
        ulonglong2 uu  = sU[iw];           // u0,u1
        ulonglong2 vv  = sV[iw];           // v0,v1
        ulonglong2 wA  = sW[5 * j + 0];
        ulonglong2 wB  = sW[5 * j + 1];
        ulonglong2 wC  = sW[5 * j + 2];
        ulonglong2 wD  = sW[5 * j + 3];
        ulonglong2 wE  = sW[5 * j + 4];

        // ---- ixpm (powers) ----
        float2 f0 = upk(uu.x);
        float2 f1 = upk(uu.y);
        float p0 = f0.x * f0.x + f0.y * f0.y;
        float p1 = f1.x * f1.x + f1.y * f1.y;
        float ps0 = 2.f * p0 + p1;
        float ps1 = 2.f * p1 + p0;
        fma2(axp, pk(ps0, ps1), wE.x);

        // ---- icixpm product: q0 = X0[p]*conj(X1[p]) ----
        ull qd = fma2r(vv.x, nsb.y, mul2(uu.x, nsb.x));
        fma2(qc, qd, wE.y);

        // ---- shift +1 products (c = p-1 splats cs1) ----
        {
            ull d;
            d = fma2r(vv.x, cs1a.y, mul2(uu.x, cs1a.x));   // D00
            fma2(Ap[0], d, wA.x); fma2(Bp[0], d, wA.y);
            fma2(Am[0], d, wC.x); fma2(Bm[0], d, wC.y);
            d = fma2r(vv.x, cs1b.y, mul2(uu.x, cs1b.x));   // D01
            fma2(Ap[1], d, wA.x); fma2(Bp[1], d, wA.y);
            fma2(Am[1], d, wC.x); fma2(Bm[1], d, wC.y);
            d = fma2r(vv.y, cs1a.y, mul2(uu.y, cs1a.x));   // D10
            fma2(Ap[2], d, wA.x); fma2(Bp[2], d, wA.y);
            fma2(Am[2], d, wC.x); fma2(Bm[2], d, wC.y);
            d = fma2r(vv.y, cs1b.y, mul2(uu.y, cs1b.x));   // D11
            fma2(Ap[3], d, wA.x); fma2(Bp[3], d, wA.y);
            fma2(Am[3], d, wC.x); fma2(Bm[3], d, wC.y);
        }
        // ---- shift +2 products (c = p-2 splats cs2) ----
        {
            ull d;
            d = fma2r(vv.x, cs2a.y, mul2(uu.x, cs2a.x));   // D00
            fma2(Ap[4], d, wB.x); fma2(Bp[4], d, wB.y);
            fma2(Am[4], d, wD.x); fma2(Bm[4], d, wD.y);
            d = fma2r(vv.x, cs2b.y, mul2(uu.x, cs2b.x));   // D01
            fma2(Ap[5], d, wB.x); fma2(Bp[5], d, wB.y);
            fma2(Am[5], d, wD.x); fma2(Bm[5], d, wD.y);
            d = fma2r(vv.y, cs2a.y, mul2(uu.y, cs2a.x));   // D10
            fma2(Ap[6], d, wB.x); fma2(Bp[6], d, wB.y);
            fma2(Am[6], d, wD.x); fma2(Bm[6], d, wD.y);
            d = fma2r(vv.y, cs2b.y, mul2(uu.y, cs2b.x));   // D11
            fma2(Ap[7], d, wB.x); fma2(Bp[7], d, wB.y);
            fma2(Am[7], d, wD.x); fma2(Bm[7], d, wD.y);
        }

        // rotate splat ring
        cs2a = cs1a; cs2b = cs1b;
        cs1a = nsa;  cs1b = nsb;
    }

    if (l < Lout) {
        float2 axpf = upk(axp);
        float2 qcf  = upk(qc);
        float axp0 = axpf.x, axp1 = axpf.y;
        float qcr = qcf.x, qci = qcf.y;

        // ---- center position floats ----
        ulonglong2 xcu = sU[t + 102];          // position l + 100
        float2 x0 = upk(xcu.x), x1 = upk(xcu.y);
        float xc_x = x0.x, xc_y = x0.y, xc_z = x1.x, xc_w = x1.y;

        // ---- center-tap corrections (zcv) ----
        float wxc = ixpm_w[HALF];
        float wqc = icixpm_w[HALF];
        float pc0 = xc_x * xc_x + xc_y * xc_y;
        float pc1 = xc_z * xc_z + xc_w * xc_w;
        axp0 -= wxc * (2.f * pc0 + pc1);
        axp1 -= wxc * (2.f * pc1 + pc0);
        qcr -= wqc * (xc_x * xc_z + xc_y * xc_w);
        qci -= wqc * (xc_y * xc_z - xc_x * xc_w);

        float spm  = C00 * (pc0 + pc1);
        float phi0 = spm + 2.f * axp0;
        float phi1 = spm + 2.f * axp1;

        // ---- ici ----
        float ici0r = -(xc_z * qci + xc_w * qcr);
        float ici0i =   xc_z * qcr - xc_w * qci;
        float ici1r =   xc_x * qci - xc_y * qcr;
        float ici1i =   xc_x * qcr + xc_y * qci;

        // ---- recombine G for the 4 shift-filters k=0..3 (s=-2,-1,1,2) ----
        float Gr[4][4], Gi[4][4];
        const int sw[4] = {0, 2, 1, 3};   // mm' -> m'm
#pragma unroll
        for (int m = 0; m < 4; ++m) {
            float2 a, bb;
            a = upk(Ap[m]); bb = upk(Bp[m]);
            Gr[2][m] = a.x - bb.y;  Gi[2][m] = a.y + bb.x;
            a = upk(Ap[4 + m]); bb = upk(Bp[4 + m]);
            Gr[3][m] = a.x - bb.y;  Gi[3][m] = a.y + bb.x;
            a = upk(Am[sw[m]]); bb = upk(Bm[sw[m]]);
            Gr[1][m] = a.x + bb.y;  Gi[1][m] = bb.x - a.y;
            a = upk(Am[4 + sw[m]]); bb = upk(Bm[4 + sw[m]]);
            Gr[0][m] = a.x + bb.y;  Gi[0][m] = bb.x - a.y;
        }

        // ---- FWM combine ----
        float fwm0r = 0.f, fwm0i = 0.f, fwm1r = 0.f, fwm1i = 0.f;
        const int soff[4] = {104, 103, 101, 100};  // s=-2,-1,1,2 -> X[l+100-s]
#pragma unroll
        for (int k = 0; k < 4; ++k) {
            ulonglong2 xsu = sU[t + soff[k]];
            float2 s0f = upk(xsu.x), s1f = upk(xsu.y);
            float xs_x = s0f.x, xs_y = s0f.y, xs_z = s1f.x, xs_w = s1f.y;
            float G00r = Gr[k][0], G00i = Gi[k][0];
            float G01r = Gr[k][1], G01i = Gi[k][1];
            float G10r = Gr[k][2], G10i = Gi[k][2];
            float G11r = Gr[k][3], G11i = Gi[k][3];
            float fA0r = 2.f * G00r + G11r, fA0i = 2.f * G00i + G11i;
            float fA1r = 2.f * G11r + G00r, fA1i = 2.f * G11i + G00i;
            fwm0r += xs_x * fA0r - xs_y * fA0i;
            fwm0i += xs_x * fA0i + xs_y * fA0r;
            fwm0r += xs_z * G01r - xs_w * G01i;
            fwm0i += xs_z * G01i + xs_w * G01r;
            fwm1r += xs_z * fA1r - xs_w * fA1i;
            fwm1i += xs_z * fA1i + xs_w * fA1r;
            fwm1r += xs_x * G10r - xs_y * G10i;
            fwm1i += xs_x * G10i + xs_y * G10r;
        }

        // ---- assemble ----
        float s0, c0, s1, c1;
        sincosf(phi0, &s0, &c0);
        sincosf(phi1, &s1, &c1);
        float o0r = xc_x * c0 - xc_y * s0 + ici0r + fwm0r;
        float o0i = xc_x * s0 + xc_y * c0 + ici0i + fwm0i;
        float o1r = xc_z * c1 - xc_w * s1 + ici1r + fwm1r;
        float o1i = xc_z * s1 + xc_w * c1 + ici1i + fwm1i;

        float4* outv = (float4*)(out + ((size_t)(b * (size_t)Lout + l)) * 4);
        *outv = make_float4(o0r * rsP, o0i * rsP, o1r * rsP, o1i * rsP);
    }
}

extern "C" void kernel_launch(void* const* d_in, const int* in_sizes, int n_in,
                              void* d_out, int out_size)
{
    const float* x_real    = (const float*)d_in[0];
    const float* x_imag    = (const float*)d_in[1];
    const float* task_info = (const float*)d_in[2];
    const float* C00       = (const float*)d_in[3];
    const float* ixpm_w    = (const float*)d_in[4];
    const float* icixpm_w  = (const float*)d_in[5];
    const float* fwm_wr    = (const float*)d_in[6];
    const float* fwm_wi    = (const float*)d_in[7];

    int B = in_sizes[2] / 4;
    int M = in_sizes[0] / (B * 2);
    int Lout = M - NTAPS + 1;

    dim3 grid((Lout + TILE - 1) / TILE, B);
    snse_kernel<<<grid, TILE>>>(x_real, x_imag, task_info, C00,
                                ixpm_w, icixpm_w, fwm_wr, fwm_wi,
                                (float*)d_out, M, Lout);
}

// round 4
// speedup vs baseline: 1.5170x; 1.0111x over previous
#include <cuda_runtime.h>
#include <math.h>

#define NTAPS 201
#define HALF  100
#define NT2   203          // extended tap loop (covers shifted-weight tails)
#define TILE  128
#define WIN   (TILE + 208)

typedef unsigned long long ull;

__device__ __forceinline__ ull pk(float lo, float hi) {
    ull r; asm("mov.b64 %0, {%1, %2};" : "=l"(r) : "f"(lo), "f"(hi)); return r;
}
__device__ __forceinline__ float2 upk(ull v) {
    float2 r; asm("mov.b64 {%0, %1}, %2;" : "=f"(r.x), "=f"(r.y) : "l"(v)); return r;
}
__device__ __forceinline__ void fma2(ull &d, ull a, ull b) {
    asm("fma.rn.f32x2 %0, %1, %2, %0;" : "+l"(d) : "l"(a), "l"(b));
}
__device__ __forceinline__ ull fma2r(ull a, ull b, ull c) {
    ull r; asm("fma.rn.f32x2 %0, %1, %2, %3;" : "=l"(r) : "l"(a), "l"(b), "l"(c)); return r;
}
__device__ __forceinline__ ull mul2(ull a, ull b) {
    ull r; asm("mul.rn.f32x2 %0, %1, %2;" : "=l"(r) : "l"(a), "l"(b)); return r;
}

// Shared layouts:
//  sU[idx]      = { (r0,i0), (r1,i1) }          natural pairs (u_m)
//  sV[idx]      = { (i0,-r0), (i1,-r1) }        rotated pairs (v_m)
//  sW[5j+0..4]  = { wrP1s|wiP1s, wrP2s|wiP2s, wrM1s|wiM1s, wrM2s|wiM2s, wxs|wqs }
// Splats of each position are built in registers from sU (4 packs/tap) and
// ring-rotated for the +1/+2 shift products.

__global__ __launch_bounds__(TILE, 3)
void snse_kernel(const float* __restrict__ x_real,
                 const float* __restrict__ x_imag,
                 const float* __restrict__ task_info,
                 const float* __restrict__ C00p,
                 const float* __restrict__ ixpm_w,
                 const float* __restrict__ icixpm_w,
                 const float* __restrict__ fwm_wr,
                 const float* __restrict__ fwm_wi,
                 float* __restrict__ out,
                 int M, int Lout)
{
    __shared__ ulonglong2 sU[WIN];
    __shared__ ulonglong2 sV[WIN];
    __shared__ ulonglong2 sW[NT2 * 5];

    const int b  = blockIdx.y;
    const int l0 = blockIdx.x * TILE;
    const int t  = threadIdx.x;

    const float dbm = task_info[b * 4];
    const float P   = exp10f(dbm * 0.1f) * 0.5f;   // /Nm, Nm=2
    const float sP  = sqrtf(P);
    const float rsP = 1.0f / sP;
    const float C00 = C00p[0];

    // ---- build pre-splatted weight table ----
    for (int j = t; j < NT2; j += TILE) {
        float wrP1 = (j <= 200) ? fwm_wr[2 * NTAPS + j] : 0.f;
        float wiP1 = (j <= 200) ? fwm_wi[2 * NTAPS + j] : 0.f;
        float wrP2 = (j <= 200) ? fwm_wr[3 * NTAPS + j] : 0.f;
        float wiP2 = (j <= 200) ? fwm_wi[3 * NTAPS + j] : 0.f;
        float wrM1 = (j >= 1 && j <= 201) ? fwm_wr[1 * NTAPS + (j - 1)] : 0.f;
        float wiM1 = (j >= 1 && j <= 201) ? fwm_wi[1 * NTAPS + (j - 1)] : 0.f;
        float wrM2 = (j >= 2) ? fwm_wr[0 * NTAPS + (j - 2)] : 0.f;
        float wiM2 = (j >= 2) ? fwm_wi[0 * NTAPS + (j - 2)] : 0.f;
        float wx   = (j <= 200) ? ixpm_w[j]   : 0.f;
        float wq   = (j <= 200) ? icixpm_w[j] : 0.f;
        sW[5 * j + 0] = make_ulonglong2(pk(wrP1, wrP1), pk(wiP1, wiP1));
        sW[5 * j + 1] = make_ulonglong2(pk(wrP2, wrP2), pk(wiP2, wiP2));
        sW[5 * j + 2] = make_ulonglong2(pk(wrM1, wrM1), pk(wiM1, wiM1));
        sW[5 * j + 3] = make_ulonglong2(pk(wrM2, wrM2), pk(wiM2, wiM2));
        sW[5 * j + 4] = make_ulonglong2(pk(wx, wx), pk(wq, wq));
    }

    // ---- load scaled x window with mod-M wrap ----
    const float* xr = x_real + (size_t)b * M * 2;
    const float* xi = x_imag + (size_t)b * M * 2;
    for (int idx = t; idx < WIN; idx += TILE) {
        int g  = l0 - 2 + idx;
        int gm = (g < 0) ? g + M : ((g >= M) ? g - M : g);
        float r0 = xr[gm * 2 + 0] * sP, r1 = xr[gm * 2 + 1] * sP;
        float i0 = xi[gm * 2 + 0] * sP, i1 = xi[gm * 2 + 1] * sP;
        sU[idx] = make_ulonglong2(pk(r0, i0), pk(r1, i1));
        sV[idx] = make_ulonglong2(pk(i0, -r0), pk(i1, -r1));
    }
    __syncthreads();

    const int l = l0 + t;

    // ---- accumulators (f32x2 pairs) ----
    ull Ap[8], Bp[8], Am[8], Bm[8];
#pragma unroll
    for (int k = 0; k < 8; ++k) { Ap[k] = Bp[k] = Am[k] = Bm[k] = 0ULL; }
    ull axp = 0ULL;   // (axp0, axp1)
    ull qc  = 0ULL;   // (qcr, qci)

    // splat rings (registers): cs2 = splats of p-2, cs1 = splats of p-1
    ull cs2r0, cs2i0, cs2r1, cs2i1;
    ull cs1r0, cs1i0, cs1r1, cs1i1;
    {
        ulonglong2 u0 = sU[t + 0];
        float2 a = upk(u0.x), c = upk(u0.y);
        cs2r0 = pk(a.x, a.x); cs2i0 = pk(a.y, a.y);
        cs2r1 = pk(c.x, c.x); cs2i1 = pk(c.y, c.y);
        ulonglong2 u1 = sU[t + 1];
        float2 d = upk(u1.x), e = upk(u1.y);
        cs1r0 = pk(d.x, d.x); cs1i0 = pk(d.y, d.y);
        cs1r1 = pk(e.x, e.x); cs1i1 = pk(e.y, e.y);
    }

#pragma unroll 2
    for (int j = 0; j < NT2; ++j) {
        const int iw = t + 2 + j;
        ulonglong2 uu  = sU[iw];           // u0,u1 at position p
        ulonglong2 vv  = sV[iw];           // v0,v1
        ulonglong2 wA  = sW[5 * j + 0];
        ulonglong2 wB  = sW[5 * j + 1];
        ulonglong2 wC  = sW[5 * j + 2];
        ulonglong2 wD  = sW[5 * j + 3];
        ulonglong2 wE  = sW[5 * j + 4];

        float2 f0 = upk(uu.x);
        float2 f1 = upk(uu.y);
        // splats of p (register packs)
        ull nsr0 = pk(f0.x, f0.x), nsi0 = pk(f0.y, f0.y);
        ull nsr1 = pk(f1.x, f1.x), nsi1 = pk(f1.y, f1.y);

        // ---- ixpm (powers) ----
        float p0 = f0.x * f0.x + f0.y * f0.y;
        float p1 = f1.x * f1.x + f1.y * f1.y;
        float ps0 = 2.f * p0 + p1;
        float ps1 = 2.f * p1 + p0;
        fma2(axp, pk(ps0, ps1), wE.x);

        // ---- icixpm product: q0 = X0[p]*conj(X1[p]) ----
        ull qd = fma2r(vv.x, nsi1, mul2(uu.x, nsr1));
        fma2(qc, qd, wE.y);

        // ---- shift +1 products (c = p-1 splats) ----
        {
            ull d;
            d = fma2r(vv.x, cs1i0, mul2(uu.x, cs1r0));   // D00
            fma2(Ap[0], d, wA.x); fma2(Bp[0], d, wA.y);
            fma2(Am[0], d, wC.x); fma2(Bm[0], d, wC.y);
            d = fma2r(vv.x, cs1i1, mul2(uu.x, cs1r1));   // D01
            fma2(Ap[1], d, wA.x); fma2(Bp[1], d, wA.y);
            fma2(Am[1], d, wC.x); fma2(Bm[1], d, wC.y);
            d = fma2r(vv.y, cs1i0, mul2(uu.y, cs1r0));   // D10
            fma2(Ap[2], d, wA.x); fma2(Bp[2], d, wA.y);
            fma2(Am[2], d, wC.x); fma2(Bm[2], d, wC.y);
            d = fma2r(vv.y, cs1i1, mul2(uu.y, cs1r1));   // D11
            fma2(Ap[3], d, wA.x); fma2(Bp[3], d, wA.y);
            fma2(Am[3], d, wC.x); fma2(Bm[3], d, wC.y);
        }
        // ---- shift +2 products (c = p-2 splats) ----
        {
            ull d;
            d = fma2r(vv.x, cs2i0, mul2(uu.x, cs2r0));   // D00
            fma2(Ap[4], d, wB.x); fma2(Bp[4], d, wB.y);
            fma2(Am[4], d, wD.x); fma2(Bm[4], d, wD.y);
            d = fma2r(vv.x, cs2i1, mul2(uu.x, cs2r1));   // D01
            fma2(Ap[5], d, wB.x); fma2(Bp[5], d, wB.y);
            fma2(Am[5], d, wD.x); fma2(Bm[5], d, wD.y);
            d = fma2r(vv.y, cs2i0, mul2(uu.y, cs2r0));   // D10
            fma2(Ap[6], d, wB.x); fma2(Bp[6], d, wB.y);
            fma2(Am[6], d, wD.x); fma2(Bm[6], d, wD.y);
            d = fma2r(vv.y, cs2i1, mul2(uu.y, cs2r1));   // D11
            fma2(Ap[7], d, wB.x); fma2(Bp[7], d, wB.y);
            fma2(Am[7], d, wD.x); fma2(Bm[7], d, wD.y);
        }

        // rotate splat ring
        cs2r0 = cs1r0; cs2i0 = cs1i0; cs2r1 = cs1r1; cs2i1 = cs1i1;
        cs1r0 = nsr0;  cs1i0 = nsi0;  cs1r1 = nsr1;  cs1i1 = nsi1;
    }

    if (l < Lout) {
        float2 axpf = upk(axp);
        float2 qcf  = upk(qc);
        float axp0 = axpf.x, axp1 = axpf.y;
        float qcr = qcf.x, qci = qcf.y;

        // ---- center position floats ----
        ulonglong2 xcu = sU[t + 102];          // position l + 100
        float2 x0 = upk(xcu.x), x1 = upk(xcu.y);
        float xc_x = x0.x, xc_y = x0.y, xc_z = x1.x, xc_w = x1.y;

        // ---- center-tap corrections (zcv) ----
        float wxc = ixpm_w[HALF];
        float wqc = icixpm_w[HALF];
        float pc0 = xc_x * xc_x + xc_y * xc_y;
        float pc1 = xc_z * xc_z + xc_w * xc_w;
        axp0 -= wxc * (2.f * pc0 + pc1);
        axp1 -= wxc * (2.f * pc1 + pc0);
        qcr -= wqc * (xc_x * xc_z + xc_y * xc_w);
        qci -= wqc * (xc_y * xc_z - xc_x * xc_w);

        float spm  = C00 * (pc0 + pc1);
        float phi0 = spm + 2.f * axp0;
        float phi1 = spm + 2.f * axp1;

        // ---- ici ----
        float ici0r = -(xc_z * qci + xc_w * qcr);
        float ici0i =   xc_z * qcr - xc_w * qci;
        float ici1r =   xc_x * qci - xc_y * qcr;
        float ici1i =   xc_x * qcr + xc_y * qci;

        // ---- recombine G for the 4 shift-filters k=0..3 (s=-2,-1,1,2) ----
        float Gr[4][4], Gi[4][4];
        const int sw[4] = {0, 2, 1, 3};   // mm' -> m'm
#pragma unroll
        for (int m = 0; m < 4; ++m) {
            float2 a, bb;
            a = upk(Ap[m]); bb = upk(Bp[m]);
            Gr[2][m] = a.x - bb.y;  Gi[2][m] = a.y + bb.x;
            a = upk(Ap[4 + m]); bb = upk(Bp[4 + m]);
            Gr[3][m] = a.x - bb.y;  Gi[3][m] = a.y + bb.x;
            a = upk(Am[sw[m]]); bb = upk(Bm[sw[m]]);
            Gr[1][m] = a.x + bb.y;  Gi[1][m] = bb.x - a.y;
            a = upk(Am[4 + sw[m]]); bb = upk(Bm[4 + sw[m]]);
            Gr[0][m] = a.x + bb.y;  Gi[0][m] = bb.x - a.y;
        }

        // ---- FWM combine ----
        float fwm0r = 0.f, fwm0i = 0.f, fwm1r = 0.f, fwm1i = 0.f;
        const int soff[4] = {104, 103, 101, 100};  // s=-2,-1,1,2 -> X[l+100-s]
#pragma unroll
        for (int k = 0; k < 4; ++k) {
            ulonglong2 xsu = sU[t + soff[k]];
            float2 s0f = upk(xsu.x), s1f = upk(xsu.y);
            float xs_x = s0f.x, xs_y = s0f.y, xs_z = s1f.x, xs_w = s1f.y;
            float G00r = Gr[k][0], G00i = Gi[k][0];
            float G01r = Gr[k][1], G01i = Gi[k][1];
            float G10r = Gr[k][2], G10i = Gi[k][2];
            float G11r = Gr[k][3], G11i = Gi[k][3];
            float fA0r = 2.f * G00r + G11r, fA0i = 2.f * G00i + G11i;
            float fA1r = 2.f * G11r + G00r, fA1i = 2.f * G11i + G00i;
            fwm0r += xs_x * fA0r - xs_y * fA0i;
            fwm0i += xs_x * fA0i + xs_y * fA0r;
            fwm0r += xs_z * G01r - xs_w * G01i;
            fwm0i += xs_z * G01i + xs_w * G01r;
            fwm1r += xs_z * fA1r - xs_w * fA1i;
            fwm1i += xs_z * fA1i + xs_w * fA1r;
            fwm1r += xs_x * G10r - xs_y * G10i;
            fwm1i += xs_x * G10i + xs_y * G10r;
        }

        // ---- assemble ----
        float s0, c0, s1, c1;
        sincosf(phi0, &s0, &c0);
        sincosf(phi1, &s1, &c1);
        float o0r = xc_x * c0 - xc_y * s0 + ici0r + fwm0r;
        float o0i = xc_x * s0 + xc_y * c0 + ici0i + fwm0i;
        float o1r = xc_z * c1 - xc_w * s1 + ici1r + fwm1r;
        float o1i = xc_z * s1 + xc_w * c1 + ici1i + fwm1i;

        float4* outv = (float4*)(out + ((size_t)(b * (size_t)Lout + l)) * 4);
        *outv = make_float4(o0r * rsP, o0i * rsP, o1r * rsP, o1i * rsP);
    }
}

extern "C" void kernel_launch(void* const* d_in, const int* in_sizes, int n_in,
                              void* d_out, int out_size)
{
    const float* x_real    = (const float*)d_in[0];
    const float* x_imag    = (const float*)d_in[1];
    const float* task_info = (const float*)d_in[2];
    const float* C00       = (const float*)d_in[3];
    const float* ixpm_w    = (const float*)d_in[4];
    const float* icixpm_w  = (const float*)d_in[5];
    const float* fwm_wr    = (const float*)d_in[6];
    const float* fwm_wi    = (const float*)d_in[7];

    int B = in_sizes[2] / 4;
    int M = in_sizes[0] / (B * 2);
    int Lout = M - NTAPS + 1;

    dim3 grid((Lout + TILE - 1) / TILE, B);
    snse_kernel<<<grid, TILE>>>(x_real, x_imag, task_info, C00,
                                ixpm_w, icixpm_w, fwm_wr, fwm_wi,
                                (float*)d_out, M, Lout);
}